// round 1
// baseline (speedup 1.0000x reference)
#include <cuda_runtime.h>
#include <math.h>

#define BB   8
#define TT   8192
#define MM   (BB * TT)        // 65536 points
#define HH   128
#define RRR  (128 * 128)      // 16384 bins
#define NBLK 5

// ---------------- scratch (device globals; no allocation allowed) ----------
__device__ float g_net0[MM * 128];
__device__ float g_net1[MM * 128];
__device__ float g_x2[MM * 128];      // proj half 2 / pooled
__device__ float g_h[MM * 128];
__device__ float g_c[MM * 128];
__device__ float g_bins[BB * RRR * 128];   // max-pool bins / mean sums (67MB)
__device__ float g_cnt[BB * RRR];
__device__ int   g_idx[3 * MM];

// ---------------- bin index -------------------------------------------------
// matches: xy = p[..,cols] / (1+EPS) + 0.5; clip(0, 1-EPS); floor(xy*R)
__device__ __forceinline__ int bin_coord(float a) {
    float v = __fdiv_rn(a, 1.001f) + 0.5f;   // IEEE div, immune to fast-math
    v = fminf(fmaxf(v, 0.0f), 0.999f);
    return (int)floorf(v * 128.0f);
}

__global__ void k_index(const float* __restrict__ p) {
    int m = blockIdx.x * blockDim.x + threadIdx.x;
    if (m >= MM) return;
    float x = p[3 * m], y = p[3 * m + 1], z = p[3 * m + 2];
    int gx = bin_coord(x), gy = bin_coord(y), gz = bin_coord(z);
    g_idx[0 * MM + m] = gx + 128 * gz;   // plane (0,2)
    g_idx[1 * MM + m] = gx + 128 * gy;   // plane (0,1)
    g_idx[2 * MM + m] = gy + 128 * gz;   // plane (1,2)
}

// ---------------- initial projection ---------------------------------------
// net = p@wp + bp  [M,256];  corr adds p2@wp2 + bp2.
// cols 0..127 -> g_net0, 128..255 -> g_x2
__global__ void k_proj(const float* __restrict__ p, const float* __restrict__ p2,
                       const float* __restrict__ wp, const float* __restrict__ bp,
                       const float* __restrict__ wp2, const float* __restrict__ bp2,
                       int corr) {
    int t = blockIdx.x * blockDim.x + threadIdx.x;
    if (t >= MM * 256) return;
    int m = t >> 8, j = t & 255;
    float x0 = p[3 * m], x1 = p[3 * m + 1], x2 = p[3 * m + 2];
    float v = bp[j] + x0 * wp[j] + x1 * wp[256 + j] + x2 * wp[512 + j];
    if (corr) {
        float y0 = p2[3 * m], y1 = p2[3 * m + 1], y2 = p2[3 * m + 2];
        v += bp2[j] + y0 * wp2[j] + y1 * wp2[256 + j] + y2 * wp2[512 + j];
    }
    float* dst = (j < 128) ? g_net0 : g_x2;
    dst[m * 128 + (j & 127)] = v;
}

// ---------------- fused multi-segment SGEMM ---------------------------------
// out[M,128] = sum_{s<nseg} act_s(A_s)[M,128] @ W_s[128,128] + bias
// act_s = relu if bit s of reluMask set. 128x128 block tile, BK=32, 8x8/thread.
__global__ __launch_bounds__(256, 2)
void k_gemm(const float* __restrict__ A0, const float* __restrict__ A1,
            const float* __restrict__ A2,
            const float* __restrict__ W0, const float* __restrict__ W1,
            const float* __restrict__ W2,
            const float* __restrict__ bias, float* __restrict__ out,
            int nseg, int reluMask) {
    __shared__ float As[32][132];   // [k][m], padded; 528B rows keep 16B align
    __shared__ float Bs[32][128];   // [k][n]

    const int m0 = blockIdx.x * 128;
    const int tid = threadIdx.x;
    const int ty = tid >> 4, tx = tid & 15;

    float acc[8][8];
#pragma unroll
    for (int i = 0; i < 8; i++)
#pragma unroll
        for (int j = 0; j < 8; j++) acc[i][j] = 0.0f;

    for (int s = 0; s < nseg; s++) {
        const float* A = (s == 0) ? A0 : (s == 1 ? A1 : A2);
        const float* W = (s == 0) ? W0 : (s == 1 ? W1 : W2);
        const bool doRelu = (reluMask >> s) & 1;

        for (int kc = 0; kc < 128; kc += 32) {
            // A tile: 128 rows x 32 k-cols, transposed into As[k][m]
#pragma unroll
            for (int it = 0; it < 4; it++) {
                int r  = it * 32 + (tid >> 3);
                int c4 = (tid & 7) * 4;
                float4 v = *(const float4*)&A[(size_t)(m0 + r) * 128 + kc + c4];
                if (doRelu) {
                    v.x = fmaxf(v.x, 0.f); v.y = fmaxf(v.y, 0.f);
                    v.z = fmaxf(v.z, 0.f); v.w = fmaxf(v.w, 0.f);
                }
                As[c4 + 0][r] = v.x; As[c4 + 1][r] = v.y;
                As[c4 + 2][r] = v.z; As[c4 + 3][r] = v.w;
            }
            // W tile: 32 k-rows x 128 n-cols
#pragma unroll
            for (int it = 0; it < 4; it++) {
                int r  = it * 8 + (tid >> 5);
                int c4 = (tid & 31) * 4;
                *(float4*)&Bs[r][c4] = *(const float4*)&W[(size_t)(kc + r) * 128 + c4];
            }
            __syncthreads();

#pragma unroll
            for (int k = 0; k < 32; k++) {
                float a[8], b[8];
                *(float4*)(a)     = *(const float4*)&As[k][ty * 8];
                *(float4*)(a + 4) = *(const float4*)&As[k][ty * 8 + 4];
                *(float4*)(b)     = *(const float4*)&Bs[k][tx * 8];
                *(float4*)(b + 4) = *(const float4*)&Bs[k][tx * 8 + 4];
#pragma unroll
                for (int i = 0; i < 8; i++)
#pragma unroll
                    for (int j = 0; j < 8; j++)
                        acc[i][j] += a[i] * b[j];
            }
            __syncthreads();
        }
    }

#pragma unroll
    for (int i = 0; i < 8; i++) {
        int row = m0 + ty * 8 + i;
#pragma unroll
        for (int j = 0; j < 8; j += 4) {
            int col = tx * 8 + j;
            float4 o;
            o.x = acc[i][j + 0] + bias[col + 0];
            o.y = acc[i][j + 1] + bias[col + 1];
            o.z = acc[i][j + 2] + bias[col + 2];
            o.w = acc[i][j + 3] + bias[col + 3];
            *(float4*)&out[(size_t)row * 128 + col] = o;
        }
    }
}

// ---------------- local max-pool -------------------------------------------
// bins pre-filled with 0xFFFFFFFF (NaN pattern; int -1 / uint max -> identity
// for the signed/unsigned atomic max trick below).
__global__ void k_scatter_max(const float* __restrict__ net,
                              const int* __restrict__ idx) {
    int m = blockIdx.x;
    int f = threadIdx.x;
    int b = m >> 13;                 // m / TT
    int bin = idx[m];
    float v = net[(size_t)m * 128 + f];
    float* addr = &g_bins[((size_t)b * RRR + bin) * 128 + f];
    if (v >= 0.0f) atomicMax((int*)addr, __float_as_int(v));
    else           atomicMin((unsigned int*)addr, __float_as_uint(v));
}

__global__ void k_gather(const int* __restrict__ idx,
                         float* __restrict__ pooled, int accum) {
    int m = blockIdx.x;
    int f = threadIdx.x;
    int b = m >> 13;
    int bin = idx[m];
    float v = g_bins[((size_t)b * RRR + bin) * 128 + f];
    if (!(fabsf(v) < INFINITY)) v = 0.0f;    // NaN (empty) or inf -> 0
    if (accum) pooled[(size_t)m * 128 + f] += v;
    else       pooled[(size_t)m * 128 + f] = v;
}

// ---------------- plane scatter-mean ---------------------------------------
__global__ void k_scatter_mean(const float* __restrict__ c,
                               const int* __restrict__ idx) {
    int m = blockIdx.x;
    int f = threadIdx.x;
    int b = m >> 13;
    int bin = idx[m];
    atomicAdd(&g_bins[((size_t)b * RRR + bin) * 128 + f], c[(size_t)m * 128 + f]);
    if (f == 0) atomicAdd(&g_cnt[(size_t)b * RRR + bin], 1.0f);
}

// out[b][ch][bin] = sums[b][bin][ch] / max(cnt,1); out base points at one plane
__global__ void k_writeout(float* __restrict__ out) {
    __shared__ float tile[32][33];
    __shared__ float cnt_s[32];
    int b = blockIdx.z;
    int bin0 = blockIdx.x * 32, ch0 = blockIdx.y * 32;
    int tx = threadIdx.x, ty = threadIdx.y;
    tile[ty][tx] = g_bins[((size_t)b * RRR + bin0 + ty) * 128 + ch0 + tx];
    if (ty == 0) cnt_s[tx] = fmaxf(g_cnt[(size_t)b * RRR + bin0 + tx], 1.0f);
    __syncthreads();
    out[((size_t)b * 128 + ch0 + ty) * RRR + bin0 + tx] =
        __fdiv_rn(tile[tx][ty], cnt_s[tx]);
}

// ---------------- orchestration --------------------------------------------
extern "C" void kernel_launch(void* const* d_in, const int* in_sizes, int n_in,
                              void* d_out, int out_size) {
    const float* p    = (const float*)d_in[0];
    const float* p2   = (const float*)d_in[1];
    const float* wp   = (const float*)d_in[2];
    const float* bp   = (const float*)d_in[3];
    const float* wp2  = (const float*)d_in[4];
    const float* bp2  = (const float*)d_in[5];
    const float* w0_all[2]  = {(const float*)d_in[6],  (const float*)d_in[11]};
    const float* b0_all[2]  = {(const float*)d_in[7],  (const float*)d_in[12]};
    const float* w1_all[2]  = {(const float*)d_in[8],  (const float*)d_in[13]};
    const float* b1_all[2]  = {(const float*)d_in[9],  (const float*)d_in[14]};
    const float* ws_all[2]  = {(const float*)d_in[10], (const float*)d_in[15]};
    const float* fcw_all[2] = {(const float*)d_in[16], (const float*)d_in[18]};
    const float* fcb_all[2] = {(const float*)d_in[17], (const float*)d_in[19]};
    float* out = (float*)d_out;

    float *net0, *net1, *x2b, *hb, *cb, *bins, *cnt;
    int* idx;
    cudaGetSymbolAddress((void**)&net0, g_net0);
    cudaGetSymbolAddress((void**)&net1, g_net1);
    cudaGetSymbolAddress((void**)&x2b,  g_x2);
    cudaGetSymbolAddress((void**)&hb,   g_h);
    cudaGetSymbolAddress((void**)&cb,   g_c);
    cudaGetSymbolAddress((void**)&bins, g_bins);
    cudaGetSymbolAddress((void**)&cnt,  g_cnt);
    cudaGetSymbolAddress((void**)&idx,  g_idx);

    const size_t binsBytes = (size_t)BB * RRR * 128 * sizeof(float);
    const size_t cntBytes  = (size_t)BB * RRR * sizeof(float);

    k_index<<<MM / 256, 256>>>(p);

    for (int st = 0; st < 2; st++) {
        const float* w0 = w0_all[st];
        const float* b0 = b0_all[st];
        const float* w1 = w1_all[st];
        const float* b1 = b1_all[st];
        const float* ws = ws_all[st];

        // projection -> halves in net0 / x2b
        k_proj<<<(MM * 256) / 256, 256>>>(p, p2, wp, bp, wp2, bp2, st);

        float* netCur = net0;
        float* netNext = net1;

        // block 0: x = (net0, x2b)
        // h = relu(x) @ w0[0] + b0[0]
        k_gemm<<<MM / 128, 256>>>(netCur, x2b, nullptr,
                                  w0, w0 + 128 * 128, nullptr,
                                  b0, hb, 2, 0b11);
        // netNext = relu(h)@w1[0] + x@ws[0] + b1[0]
        k_gemm<<<MM / 128, 256>>>(hb, netCur, x2b,
                                  w1, ws, ws + 128 * 128,
                                  b1, netNext, 3, 0b001);
        { float* t = netCur; netCur = netNext; netNext = t; }

        for (int i = 1; i < NBLK; i++) {
            // pooled (x2b) = sum over planes of gather(scatter_max(netCur))
            for (int pl = 0; pl < 3; pl++) {
                cudaMemsetAsync(bins, 0xFF, binsBytes);
                k_scatter_max<<<MM, 128>>>(netCur, idx + pl * MM);
                k_gather<<<MM, 128>>>(idx + pl * MM, x2b, pl > 0);
            }
            const float* w0i = w0 + (size_t)i * 256 * 128;
            const float* b0i = b0 + (size_t)i * 128;
            const float* w1i = w1 + (size_t)i * 128 * 128;
            const float* b1i = b1 + (size_t)i * 128;
            const float* wsi = ws + (size_t)i * 256 * 128;

            k_gemm<<<MM / 128, 256>>>(netCur, x2b, nullptr,
                                      w0i, w0i + 128 * 128, nullptr,
                                      b0i, hb, 2, 0b11);
            k_gemm<<<MM / 128, 256>>>(hb, netCur, x2b,
                                      w1i, wsi, wsi + 128 * 128,
                                      b1i, netNext, 3, 0b001);
            { float* t = netCur; netCur = netNext; netNext = t; }
        }

        // c = netCur @ fc_w + fc_b  (no relu)
        k_gemm<<<MM / 128, 256>>>(netCur, nullptr, nullptr,
                                  fcw_all[st], nullptr, nullptr,
                                  fcb_all[st], cb, 1, 0);

        // plane features: scatter-mean + transpose writeout
        for (int pl = 0; pl < 3; pl++) {
            cudaMemsetAsync(bins, 0, binsBytes);
            cudaMemsetAsync(cnt, 0, cntBytes);
            k_scatter_mean<<<MM, 128>>>(cb, idx + pl * MM);
            int plane6 = st * 3 + pl;
            k_writeout<<<dim3(RRR / 32, 128 / 32, BB), dim3(32, 32)>>>(
                out + (size_t)plane6 * BB * 128 * RRR);
        }
    }
}

// round 2
// speedup vs baseline: 1.1978x; 1.1978x over previous
#include <cuda_runtime.h>
#include <math.h>

#define BB   8
#define TT   8192
#define MM   (BB * TT)        // 65536 points per stream
#define RRR  (128 * 128)      // 16384 bins
#define NBLK 5

typedef unsigned long long u64;

// ---------------- scratch (device globals; no allocation allowed) ----------
// activation buffers are [2][M][128]: stream 0 then stream 1
__device__ float g_net0[2 * MM * 128];
__device__ float g_net1[2 * MM * 128];
__device__ float g_x2[2 * MM * 128];      // proj half 2 / pooled
__device__ float g_h[2 * MM * 128];
__device__ float g_c[2 * MM * 128];
// bins[s][pl][b][bin][f] : 2*3*8*16384*128 floats (~403 MB)
__device__ float g_bins[2 * 3 * BB * RRR * 128];
__device__ float g_cnt[3 * BB * RRR];
__device__ int   g_idx[3 * MM];

// ---------------- bin index -------------------------------------------------
__device__ __forceinline__ int bin_coord(float a) {
    float v = __fdiv_rn(a, 1.001f) + 0.5f;   // IEEE div, immune to fast-math
    v = fminf(fmaxf(v, 0.0f), 0.999f);
    return (int)floorf(v * 128.0f);
}

__global__ void k_index(const float* __restrict__ p) {
    int m = blockIdx.x * blockDim.x + threadIdx.x;
    if (m >= MM) return;
    float x = p[3 * m], y = p[3 * m + 1], z = p[3 * m + 2];
    int gx = bin_coord(x), gy = bin_coord(y), gz = bin_coord(z);
    int b = m >> 13;
    int i0 = gx + 128 * gz, i1 = gx + 128 * gy, i2 = gy + 128 * gz;
    g_idx[0 * MM + m] = i0;
    g_idx[1 * MM + m] = i1;
    g_idx[2 * MM + m] = i2;
    // counts (indices are round-invariant; computed once)
    atomicAdd(&g_cnt[(0 * BB + b) * RRR + i0], 1.0f);
    atomicAdd(&g_cnt[(1 * BB + b) * RRR + i1], 1.0f);
    atomicAdd(&g_cnt[(2 * BB + b) * RRR + i2], 1.0f);
}

// ---------------- initial projection (both streams) -------------------------
__global__ void k_proj(const float* __restrict__ p, const float* __restrict__ p2,
                       const float* __restrict__ wp, const float* __restrict__ bp,
                       const float* __restrict__ wp2, const float* __restrict__ bp2) {
    long long t = (long long)blockIdx.x * blockDim.x + threadIdx.x;  // 2*MM*256
    int s = (int)(t >> 24);                  // MM*256 == 2^24
    int m = (int)((t >> 8) & (MM - 1));
    int j = (int)(t & 255);
    float x0 = p[3 * m], x1 = p[3 * m + 1], x2 = p[3 * m + 2];
    float v = bp[j] + x0 * wp[j] + x1 * wp[256 + j] + x2 * wp[512 + j];
    if (s) {
        float y0 = p2[3 * m], y1 = p2[3 * m + 1], y2 = p2[3 * m + 2];
        v += bp2[j] + y0 * wp2[j] + y1 * wp2[256 + j] + y2 * wp2[512 + j];
    }
    float* dst = (j < 128) ? g_net0 : g_x2;
    dst[((size_t)s * MM + m) * 128 + (j & 127)] = v;
}

// ---------------- fused multi-segment SGEMM with FFMA2 ----------------------
// out[z][M,128] = sum_s act_s(A_s[z])[M,128] @ W_s[z][128,128] + bias[z]
struct GemmArgs {
    const float *A0, *A1, *A2;           // stream-0 base; stream-1 at +MM*128
    const float *W0[2], *W1[2], *W2[2];  // per-stream weights
    const float *bias[2];
    float* out;                          // stream-1 at +MM*128
    int nseg, reluMask;
};

__global__ __launch_bounds__(256, 2)
void k_gemm(GemmArgs args) {
    __shared__ float As[32][132];   // [k][m], padded
    __shared__ float Bs[32][128];   // [k][n]

    const int z = blockIdx.z;
    const size_t zo = (size_t)z * MM * 128;
    const int m0 = blockIdx.x * 128;
    const int tid = threadIdx.x;
    const int ty = tid >> 4, tx = tid & 15;

    u64 acc2[8][4];
#pragma unroll
    for (int i = 0; i < 8; i++)
#pragma unroll
        for (int j = 0; j < 4; j++) acc2[i][j] = 0ull;

    for (int s = 0; s < args.nseg; s++) {
        const float* A = ((s == 0) ? args.A0 : (s == 1 ? args.A1 : args.A2)) + zo;
        const float* W = (s == 0) ? args.W0[z] : (s == 1 ? args.W1[z] : args.W2[z]);
        const bool doRelu = (args.reluMask >> s) & 1;

        for (int kc = 0; kc < 128; kc += 32) {
#pragma unroll
            for (int it = 0; it < 4; it++) {
                int r  = it * 32 + (tid >> 3);
                int c4 = (tid & 7) * 4;
                float4 v = *(const float4*)&A[(size_t)(m0 + r) * 128 + kc + c4];
                if (doRelu) {
                    v.x = fmaxf(v.x, 0.f); v.y = fmaxf(v.y, 0.f);
                    v.z = fmaxf(v.z, 0.f); v.w = fmaxf(v.w, 0.f);
                }
                As[c4 + 0][r] = v.x; As[c4 + 1][r] = v.y;
                As[c4 + 2][r] = v.z; As[c4 + 3][r] = v.w;
            }
#pragma unroll
            for (int it = 0; it < 4; it++) {
                int r  = it * 8 + (tid >> 5);
                int c4 = (tid & 31) * 4;
                *(float4*)&Bs[r][c4] = *(const float4*)&W[(size_t)(kc + r) * 128 + c4];
            }
            __syncthreads();

#pragma unroll
            for (int k = 0; k < 32; k++) {
                float a[8];
                *(float4*)(a)     = *(const float4*)&As[k][ty * 8];
                *(float4*)(a + 4) = *(const float4*)&As[k][ty * 8 + 4];
                u64 bv[4];
                *(ulonglong2*)(bv)     = *(const ulonglong2*)&Bs[k][tx * 8];
                *(ulonglong2*)(bv + 2) = *(const ulonglong2*)&Bs[k][tx * 8 + 4];
#pragma unroll
                for (int i = 0; i < 8; i++) {
                    u64 ad;
                    asm("mov.b64 %0, {%1, %1};" : "=l"(ad) : "f"(a[i]));
#pragma unroll
                    for (int j = 0; j < 4; j++)
                        asm("fma.rn.f32x2 %0, %1, %2, %0;"
                            : "+l"(acc2[i][j]) : "l"(ad), "l"(bv[j]));
                }
            }
            __syncthreads();
        }
    }

    const float* bias = args.bias[z];
    float* out = args.out + zo;
#pragma unroll
    for (int i = 0; i < 8; i++) {
        int row = m0 + ty * 8 + i;
        float o[8];
#pragma unroll
        for (int j = 0; j < 4; j++)
            asm("mov.b64 {%0, %1}, %2;" : "=f"(o[2 * j]), "=f"(o[2 * j + 1])
                                        : "l"(acc2[i][j]));
        int col = tx * 8;
        float4 v0, v1;
        v0.x = o[0] + bias[col + 0]; v0.y = o[1] + bias[col + 1];
        v0.z = o[2] + bias[col + 2]; v0.w = o[3] + bias[col + 3];
        v1.x = o[4] + bias[col + 4]; v1.y = o[5] + bias[col + 5];
        v1.z = o[6] + bias[col + 6]; v1.w = o[7] + bias[col + 7];
        *(float4*)&out[(size_t)row * 128 + col]     = v0;
        *(float4*)&out[(size_t)row * 128 + col + 4] = v1;
    }
}

// ---------------- local max-pool (3 planes x 2 streams fused) ---------------
// bins pre-memset 0xFF (NaN pattern = identity for signed/unsigned atomic trick)
__global__ void k_scatter_max3(const float* __restrict__ net) {
    int r = blockIdx.x * 2 + threadIdx.y;   // row over 2*MM
    int f = threadIdx.x;
    int s = r >> 16;
    int m = r & (MM - 1);
    int b = m >> 13;
    float v = net[(size_t)r * 128 + f];
    int ivi = __float_as_int(v);
    unsigned uvi = __float_as_uint(v);
    bool pos = (v >= 0.0f);
#pragma unroll
    for (int pl = 0; pl < 3; pl++) {
        int bin = g_idx[pl * MM + m];
        float* addr = &g_bins[((((size_t)s * 3 + pl) * BB + b) * RRR + bin) * 128 + f];
        if (pos) atomicMax((int*)addr, ivi);
        else     atomicMin((unsigned int*)addr, uvi);
    }
}

__global__ void k_gather3(float* __restrict__ pooled) {
    int r = blockIdx.x * 2 + threadIdx.y;
    int f = threadIdx.x;
    int s = r >> 16;
    int m = r & (MM - 1);
    int b = m >> 13;
    float acc = 0.0f;
#pragma unroll
    for (int pl = 0; pl < 3; pl++) {
        int bin = g_idx[pl * MM + m];
        float v = g_bins[((((size_t)s * 3 + pl) * BB + b) * RRR + bin) * 128 + f];
        if (fabsf(v) < INFINITY) acc += v;   // NaN (empty) contributes 0
    }
    pooled[(size_t)r * 128 + f] = acc;
}

// ---------------- plane scatter-mean (both streams, 3 planes) ---------------
__global__ void k_scatter_mean3(const float* __restrict__ c) {
    int r = blockIdx.x * 2 + threadIdx.y;
    int f = threadIdx.x;
    int s = r >> 16;
    int m = r & (MM - 1);
    int b = m >> 13;
    float v = c[(size_t)r * 128 + f];
#pragma unroll
    for (int pl = 0; pl < 3; pl++) {
        int bin = g_idx[pl * MM + m];
        atomicAdd(&g_bins[((((size_t)s * 3 + pl) * BB + b) * RRR + bin) * 128 + f], v);
    }
}

// out[plane6][b][ch][bin] = sums / max(cnt,1); covers entire d_out
__global__ void k_writeout(float* __restrict__ out) {
    __shared__ float tile[32][33];
    __shared__ float cnt_s[32];
    int zi = blockIdx.z;           // 6*BB
    int plane6 = zi >> 3;          // /BB
    int b = zi & 7;
    int pl = plane6 % 3;           // s*3+pl layout matches bins layout directly
    int bin0 = blockIdx.x * 32, ch0 = blockIdx.y * 32;
    int tx = threadIdx.x, ty = threadIdx.y;
    tile[ty][tx] = g_bins[(((size_t)plane6 * BB + b) * RRR + bin0 + ty) * 128 + ch0 + tx];
    if (ty == 0) cnt_s[tx] = fmaxf(g_cnt[((size_t)pl * BB + b) * RRR + bin0 + tx], 1.0f);
    __syncthreads();
    out[(((size_t)plane6 * BB + b) * 128 + ch0 + ty) * RRR + bin0 + tx] =
        __fdiv_rn(tile[tx][ty], cnt_s[tx]);
}

// ---------------- orchestration --------------------------------------------
extern "C" void kernel_launch(void* const* d_in, const int* in_sizes, int n_in,
                              void* d_out, int out_size) {
    const float* p    = (const float*)d_in[0];
    const float* p2   = (const float*)d_in[1];
    const float* wp   = (const float*)d_in[2];
    const float* bp   = (const float*)d_in[3];
    const float* wp2  = (const float*)d_in[4];
    const float* bp2  = (const float*)d_in[5];
    const float* w0_all[2]  = {(const float*)d_in[6],  (const float*)d_in[11]};
    const float* b0_all[2]  = {(const float*)d_in[7],  (const float*)d_in[12]};
    const float* w1_all[2]  = {(const float*)d_in[8],  (const float*)d_in[13]};
    const float* b1_all[2]  = {(const float*)d_in[9],  (const float*)d_in[14]};
    const float* ws_all[2]  = {(const float*)d_in[10], (const float*)d_in[15]};
    const float* fcw_all[2] = {(const float*)d_in[16], (const float*)d_in[18]};
    const float* fcb_all[2] = {(const float*)d_in[17], (const float*)d_in[19]};
    float* out = (float*)d_out;

    float *net0, *net1, *x2b, *hb, *cb, *bins, *cnt;
    cudaGetSymbolAddress((void**)&net0, g_net0);
    cudaGetSymbolAddress((void**)&net1, g_net1);
    cudaGetSymbolAddress((void**)&x2b,  g_x2);
    cudaGetSymbolAddress((void**)&hb,   g_h);
    cudaGetSymbolAddress((void**)&cb,   g_c);
    cudaGetSymbolAddress((void**)&bins, g_bins);
    cudaGetSymbolAddress((void**)&cnt,  g_cnt);

    const size_t binsBytes = (size_t)2 * 3 * BB * RRR * 128 * sizeof(float);
    const size_t cntBytes  = (size_t)3 * BB * RRR * sizeof(float);

    cudaMemsetAsync(cnt, 0, cntBytes);
    k_index<<<MM / 256, 256>>>(p);
    k_proj<<<(2 * MM * 256) / 256, 256>>>(p, p2, wp, bp, wp2, bp2);

    float* netCur = net0;
    float* netNext = net1;
    const dim3 gemmGrid(MM / 128, 1, 2);
    const dim3 rowBlk(128, 2);

    // --- block 0: x = [netCur | x2b] ---
    {
        GemmArgs a{};
        a.A0 = netCur; a.A1 = x2b;
        for (int z = 0; z < 2; z++) {
            const float* w0 = z ? w0_all[1] : w0_all[0];
            a.W0[z] = w0; a.W1[z] = w0 + 128 * 128;
            a.bias[z] = z ? b0_all[1] : b0_all[0];
        }
        a.out = hb; a.nseg = 2; a.reluMask = 0b11;
        k_gemm<<<gemmGrid, 256>>>(a);
    }
    {
        GemmArgs a{};
        a.A0 = hb; a.A1 = netCur; a.A2 = x2b;
        for (int z = 0; z < 2; z++) {
            a.W0[z] = w1_all[z];
            a.W1[z] = ws_all[z];
            a.W2[z] = ws_all[z] + 128 * 128;
            a.bias[z] = b1_all[z];
        }
        a.out = netNext; a.nseg = 3; a.reluMask = 0b001;
        k_gemm<<<gemmGrid, 256>>>(a);
    }
    { float* t = netCur; netCur = netNext; netNext = t; }

    for (int i = 1; i < NBLK; i++) {
        cudaMemsetAsync(bins, 0xFF, binsBytes);
        k_scatter_max3<<<MM, rowBlk>>>(netCur);   // 2*MM rows, 2 rows/block
        k_gather3<<<MM, rowBlk>>>(x2b);

        {
            GemmArgs a{};
            a.A0 = netCur; a.A1 = x2b;
            for (int z = 0; z < 2; z++) {
                const float* w0i = w0_all[z] + (size_t)i * 256 * 128;
                a.W0[z] = w0i; a.W1[z] = w0i + 128 * 128;
                a.bias[z] = b0_all[z] + (size_t)i * 128;
            }
            a.out = hb; a.nseg = 2; a.reluMask = 0b11;
            k_gemm<<<gemmGrid, 256>>>(a);
        }
        {
            GemmArgs a{};
            a.A0 = hb; a.A1 = netCur; a.A2 = x2b;
            for (int z = 0; z < 2; z++) {
                const float* wsi = ws_all[z] + (size_t)i * 256 * 128;
                a.W0[z] = w1_all[z] + (size_t)i * 128 * 128;
                a.W1[z] = wsi;
                a.W2[z] = wsi + 128 * 128;
                a.bias[z] = b1_all[z] + (size_t)i * 128;
            }
            a.out = netNext; a.nseg = 3; a.reluMask = 0b001;
            k_gemm<<<gemmGrid, 256>>>(a);
        }
        { float* t = netCur; netCur = netNext; netNext = t; }
    }

    // c = netCur @ fc_w + fc_b
    {
        GemmArgs a{};
        a.A0 = netCur;
        for (int z = 0; z < 2; z++) { a.W0[z] = fcw_all[z]; a.bias[z] = fcb_all[z]; }
        a.out = cb; a.nseg = 1; a.reluMask = 0;
        k_gemm<<<gemmGrid, 256>>>(a);
    }

    // plane scatter-mean + transpose writeout for all 6 planes
    cudaMemsetAsync(bins, 0, binsBytes);
    k_scatter_mean3<<<MM, rowBlk>>>(cb);
    k_writeout<<<dim3(RRR / 32, 128 / 32, 6 * BB), dim3(32, 32)>>>(out);
}

// round 8
// speedup vs baseline: 1.6458x; 1.3740x over previous
#include <cuda_runtime.h>
#include <cuda_bf16.h>
#include <math.h>
#include <stdint.h>

#define BB   8
#define TT   8192
#define MM   (BB * TT)        // 65536 points per stream
#define RRR  (128 * 128)      // 16384 bins
#define NBLK 5

typedef unsigned long long u64;

// ---------------- scratch (device globals; no allocation allowed) ----------
__device__ float g_net0[2 * MM * 128];
__device__ float g_net1[2 * MM * 128];
__device__ float g_x2[2 * MM * 128];      // proj half 2 / pooled
__device__ float g_h[2 * MM * 128];
__device__ float g_c[2 * MM * 128];
__device__ float g_bins[2 * 3 * BB * RRR * 128];   // ~403 MB
__device__ float g_cnt[3 * BB * RRR];
__device__ int   g_idx[3 * MM];
// prepped weights: 52 slots x (hi 32KB + lo 32KB), swizzled [k][n] bf16 image
__device__ __nv_bfloat16 g_wprep[52 * 2 * 16384];

__device__ __forceinline__ uint32_t smem_u32(const void* p) {
    uint32_t a;
    asm("{ .reg .u64 t; cvta.to.shared.u64 t, %1; cvt.u32.u64 %0, t; }"
        : "=r"(a) : "l"(p));
    return a;
}

// ---------------- HMMA helpers (sm_80 baseline ISA; no arch-specific feats) -
#define LDSM4(r, a) \
    asm volatile("ldmatrix.sync.aligned.m8n8.x4.shared.b16 {%0,%1,%2,%3}, [%4];" \
        : "=r"((r)[0]), "=r"((r)[1]), "=r"((r)[2]), "=r"((r)[3]) : "r"(a))
#define LDSM4T(r, a) \
    asm volatile("ldmatrix.sync.aligned.m8n8.x4.trans.shared.b16 {%0,%1,%2,%3}, [%4];" \
        : "=r"((r)[0]), "=r"((r)[1]), "=r"((r)[2]), "=r"((r)[3]) : "r"(a))
#define MMA_BF16(c, a, b0v, b1v) \
    asm volatile("mma.sync.aligned.m16n8k16.row.col.f32.bf16.bf16.f32 " \
        "{%0,%1,%2,%3},{%4,%5,%6,%7},{%8,%9},{%0,%1,%2,%3};" \
        : "+f"((c)[0]), "+f"((c)[1]), "+f"((c)[2]), "+f"((c)[3]) \
        : "r"((a)[0]), "r"((a)[1]), "r"((a)[2]), "r"((a)[3]), "r"(b0v), "r"(b1v))

// ---------------- bin index -------------------------------------------------
__device__ __forceinline__ int bin_coord(float a) {
    float v = __fdiv_rn(a, 1.001f) + 0.5f;
    v = fminf(fmaxf(v, 0.0f), 0.999f);
    return (int)floorf(v * 128.0f);
}

__global__ void k_index(const float* __restrict__ p) {
    int m = blockIdx.x * blockDim.x + threadIdx.x;
    if (m >= MM) return;
    float x = p[3 * m], y = p[3 * m + 1], z = p[3 * m + 2];
    int gx = bin_coord(x), gy = bin_coord(y), gz = bin_coord(z);
    int b = m >> 13;
    int i0 = gx + 128 * gz, i1 = gx + 128 * gy, i2 = gy + 128 * gz;
    g_idx[0 * MM + m] = i0;
    g_idx[1 * MM + m] = i1;
    g_idx[2 * MM + m] = i2;
    atomicAdd(&g_cnt[(0 * BB + b) * RRR + i0], 1.0f);
    atomicAdd(&g_cnt[(1 * BB + b) * RRR + i1], 1.0f);
    atomicAdd(&g_cnt[(2 * BB + b) * RRR + i2], 1.0f);
}

// ---------------- initial projection (both streams) -------------------------
__global__ void k_proj(const float* __restrict__ p, const float* __restrict__ p2,
                       const float* __restrict__ wp, const float* __restrict__ bp,
                       const float* __restrict__ wp2, const float* __restrict__ bp2) {
    long long t = (long long)blockIdx.x * blockDim.x + threadIdx.x;
    int s = (int)(t >> 24);
    int m = (int)((t >> 8) & (MM - 1));
    int j = (int)(t & 255);
    float x0 = p[3 * m], x1 = p[3 * m + 1], x2 = p[3 * m + 2];
    float v = bp[j] + x0 * wp[j] + x1 * wp[256 + j] + x2 * wp[512 + j];
    if (s) {
        float y0 = p2[3 * m], y1 = p2[3 * m + 1], y2 = p2[3 * m + 2];
        v += bp2[j] + y0 * wp2[j] + y1 * wp2[256 + j] + y2 * wp2[512 + j];
    }
    float* dst = (j < 128) ? g_net0 : g_x2;
    dst[((size_t)s * MM + m) * 128 + (j & 127)] = v;
}

// ---------------- weight prep: fp32 -> bf16 hi/lo, swizzled [k][n] image ----
// byte(k,n) = k*256 + (((n>>3) ^ (k&7))<<4) + (n&7)*2
struct WSrc { const float* src[52]; };

__global__ void k_wprep(WSrc ws) {
    int s = blockIdx.y;
    int e = blockIdx.x * 256 + threadIdx.x;   // 0..16383
    int k = e >> 7, n = e & 127;
    float w = ws.src[s][k * 128 + n];
    __nv_bfloat16 hi = __float2bfloat16_rn(w);
    __nv_bfloat16 lo = __float2bfloat16_rn(w - __bfloat162float(hi));
    uint32_t off = (uint32_t)k * 256 + ((((uint32_t)n >> 3) ^ ((uint32_t)k & 7)) << 4)
                 + ((uint32_t)n & 7) * 2;
    char* base = (char*)g_wprep + (size_t)s * 65536;
    *(__nv_bfloat16*)(base + off) = hi;
    *(__nv_bfloat16*)(base + 32768 + off) = lo;
}

// ---------------- HMMA multi-segment GEMM -----------------------------------
// out[z][M,128] = sum_s act_s(A_s[z])[M,128] @ W_s[z][128,128] + bias[z]
// bf16 split: hi*hi + hi*lo + lo*hi, fp32 accumulate in registers.
struct GArgs {
    const float* A[3];
    int slot[3][2];
    const float* bias[2];
    float* out;
    int nseg, reluMask;
};

#define SA_HI 0
#define SA_LO 32768
#define SW_HI 65536
#define SW_LO 98304
#define SM_TOTAL 131072

__device__ __forceinline__ uint32_t pack_hi_lo(float x, float y, uint32_t& lo) {
    __nv_bfloat162 h = __floats2bfloat162_rn(x, y);
    float2 f = __bfloat1622float2(h);
    __nv_bfloat162 l = __floats2bfloat162_rn(x - f.x, y - f.y);
    lo = *(uint32_t*)&l;
    return *(uint32_t*)&h;
}

__global__ __launch_bounds__(256, 1)
void k_hgemm(GArgs args) {
    extern __shared__ char smem[];
    const uint32_t sb = smem_u32(smem);
    const int tid = threadIdx.x;
    const int wid = tid >> 5, lane = tid & 31;
    const int z = blockIdx.z;
    const size_t zo = (size_t)z * MM * 128;
    const int m0 = blockIdx.x * 128;
    const int warpM = (wid & 3) * 32;
    const int warpN = (wid >> 2) * 64;

    float acc[2][8][4];
#pragma unroll
    for (int mi = 0; mi < 2; mi++)
#pragma unroll
        for (int ni = 0; ni < 8; ni++)
#pragma unroll
            for (int e = 0; e < 4; e++) acc[mi][ni][e] = 0.0f;

    for (int s = 0; s < args.nseg; s++) {
        const float* A = args.A[s] + zo;
        const bool doRelu = (args.reluMask >> s) & 1;
        // --- A tile: fp32 -> relu -> bf16 hi/lo, swizzled 16B granules ---
#pragma unroll
        for (int i = 0; i < 8; i++) {
            int q = tid + i * 256;          // 0..2047 granules (128 rows x 16)
            int row = q >> 4, g = q & 15;
            const float4* src = (const float4*)&A[(size_t)(m0 + row) * 128 + g * 8];
            float4 v0 = src[0], v1 = src[1];
            if (doRelu) {
                v0.x = fmaxf(v0.x, 0.f); v0.y = fmaxf(v0.y, 0.f);
                v0.z = fmaxf(v0.z, 0.f); v0.w = fmaxf(v0.w, 0.f);
                v1.x = fmaxf(v1.x, 0.f); v1.y = fmaxf(v1.y, 0.f);
                v1.z = fmaxf(v1.z, 0.f); v1.w = fmaxf(v1.w, 0.f);
            }
            uint4 hv, lv;
            hv.x = pack_hi_lo(v0.x, v0.y, lv.x);
            hv.y = pack_hi_lo(v0.z, v0.w, lv.y);
            hv.z = pack_hi_lo(v1.x, v1.y, lv.z);
            hv.w = pack_hi_lo(v1.z, v1.w, lv.w);
            uint32_t off = (uint32_t)row * 256 + (((uint32_t)(g ^ (row & 7))) << 4);
            *(uint4*)(smem + SA_HI + off) = hv;
            *(uint4*)(smem + SA_LO + off) = lv;
        }
        // --- W tiles: linear copy of prepped swizzled image (hi+lo 64KB) ---
        const uint4* wsrc = (const uint4*)((const char*)g_wprep
                                           + (size_t)args.slot[s][z] * 65536);
#pragma unroll
        for (int i = 0; i < 8; i++) {
            int q = tid + i * 256;          // 0..2047
            ((uint4*)(smem + SW_HI))[q] = wsrc[q];
            ((uint4*)(smem + SW_LO))[q] = wsrc[q + 2048];
        }
        __syncthreads();

        // --- mainloop: 8 k16 chunks ---
#pragma unroll
        for (int kc = 0; kc < 8; kc++) {
            uint32_t ah[2][4], al[2][4];
#pragma unroll
            for (int mi = 0; mi < 2; mi++) {
                int row = warpM + mi * 16 + (lane & 15);
                int gr = kc * 2 + (lane >> 4);
                uint32_t ad = sb + (uint32_t)row * 256
                            + (((uint32_t)(gr ^ (row & 7))) << 4);
                LDSM4(ah[mi], ad + SA_HI);
                LDSM4(al[mi], ad + SA_LO);
            }
            uint32_t bh[4][4], bl[4][4];
#pragma unroll
            for (int j = 0; j < 4; j++) {
                int krow = kc * 16 + (lane & 7) + (lane & 8);
                int ng = ((warpN + j * 16) >> 3) + (lane >> 4);
                uint32_t ad = sb + (uint32_t)krow * 256
                            + (((uint32_t)(ng ^ (krow & 7))) << 4);
                LDSM4T(bh[j], ad + SW_HI);
                LDSM4T(bl[j], ad + SW_LO);
            }
#pragma unroll
            for (int mi = 0; mi < 2; mi++)
#pragma unroll
                for (int j = 0; j < 4; j++) {
                    MMA_BF16(acc[mi][2 * j],     ah[mi], bh[j][0], bh[j][1]);
                    MMA_BF16(acc[mi][2 * j],     ah[mi], bl[j][0], bl[j][1]);
                    MMA_BF16(acc[mi][2 * j],     al[mi], bh[j][0], bh[j][1]);
                    MMA_BF16(acc[mi][2 * j + 1], ah[mi], bh[j][2], bh[j][3]);
                    MMA_BF16(acc[mi][2 * j + 1], ah[mi], bl[j][2], bl[j][3]);
                    MMA_BF16(acc[mi][2 * j + 1], al[mi], bh[j][2], bh[j][3]);
                }
        }
        __syncthreads();
    }

    // --- epilogue: acc + bias -> out ---
    const float* bias = args.bias[z];
    float* out = args.out + zo;
#pragma unroll
    for (int mi = 0; mi < 2; mi++)
#pragma unroll
        for (int ni = 0; ni < 8; ni++) {
            int col = warpN + ni * 8 + (lane & 3) * 2;
            int r0 = m0 + warpM + mi * 16 + (lane >> 2);
            float2 v0, v1;
            v0.x = acc[mi][ni][0] + bias[col];
            v0.y = acc[mi][ni][1] + bias[col + 1];
            v1.x = acc[mi][ni][2] + bias[col];
            v1.y = acc[mi][ni][3] + bias[col + 1];
            *(float2*)&out[(size_t)r0 * 128 + col] = v0;
            *(float2*)&out[(size_t)(r0 + 8) * 128 + col] = v1;
        }
}

// ---------------- local max-pool (3 planes x 2 streams fused) ---------------
__global__ void k_scatter_max3(const float* __restrict__ net) {
    int r = blockIdx.x * 2 + threadIdx.y;
    int f = threadIdx.x;
    int s = r >> 16;
    int m = r & (MM - 1);
    int b = m >> 13;
    float v = net[(size_t)r * 128 + f];
    int ivi = __float_as_int(v);
    unsigned uvi = __float_as_uint(v);
    bool pos = (v >= 0.0f);
#pragma unroll
    for (int pl = 0; pl < 3; pl++) {
        int bin = g_idx[pl * MM + m];
        float* addr = &g_bins[((((size_t)s * 3 + pl) * BB + b) * RRR + bin) * 128 + f];
        if (pos) atomicMax((int*)addr, ivi);
        else     atomicMin((unsigned int*)addr, uvi);
    }
}

__global__ void k_gather3(float* __restrict__ pooled) {
    int r = blockIdx.x * 2 + threadIdx.y;
    int f = threadIdx.x;
    int s = r >> 16;
    int m = r & (MM - 1);
    int b = m >> 13;
    float acc = 0.0f;
#pragma unroll
    for (int pl = 0; pl < 3; pl++) {
        int bin = g_idx[pl * MM + m];
        float v = g_bins[((((size_t)s * 3 + pl) * BB + b) * RRR + bin) * 128 + f];
        if (fabsf(v) < INFINITY) acc += v;
    }
    pooled[(size_t)r * 128 + f] = acc;
}

// ---------------- plane scatter-mean (both streams, 3 planes) ---------------
__global__ void k_scatter_mean3(const float* __restrict__ c) {
    int r = blockIdx.x * 2 + threadIdx.y;
    int f = threadIdx.x;
    int s = r >> 16;
    int m = r & (MM - 1);
    int b = m >> 13;
    float v = c[(size_t)r * 128 + f];
#pragma unroll
    for (int pl = 0; pl < 3; pl++) {
        int bin = g_idx[pl * MM + m];
        atomicAdd(&g_bins[((((size_t)s * 3 + pl) * BB + b) * RRR + bin) * 128 + f], v);
    }
}

__global__ void k_writeout(float* __restrict__ out) {
    __shared__ float tile[32][33];
    __shared__ float cnt_s[32];
    int zi = blockIdx.z;
    int plane6 = zi >> 3;
    int b = zi & 7;
    int pl = plane6 % 3;
    int bin0 = blockIdx.x * 32, ch0 = blockIdx.y * 32;
    int tx = threadIdx.x, ty = threadIdx.y;
    tile[ty][tx] = g_bins[(((size_t)plane6 * BB + b) * RRR + bin0 + ty) * 128 + ch0 + tx];
    if (ty == 0) cnt_s[tx] = fmaxf(g_cnt[((size_t)pl * BB + b) * RRR + bin0 + tx], 1.0f);
    __syncthreads();
    out[(((size_t)plane6 * BB + b) * 128 + ch0 + ty) * RRR + bin0 + tx] =
        __fdiv_rn(tile[tx][ty], cnt_s[tx]);
}

// ---------------- orchestration --------------------------------------------
extern "C" void kernel_launch(void* const* d_in, const int* in_sizes, int n_in,
                              void* d_out, int out_size) {
    const float* p    = (const float*)d_in[0];
    const float* p2   = (const float*)d_in[1];
    const float* wp   = (const float*)d_in[2];
    const float* bp   = (const float*)d_in[3];
    const float* wp2  = (const float*)d_in[4];
    const float* bp2  = (const float*)d_in[5];
    const float* w0_all[2]  = {(const float*)d_in[6],  (const float*)d_in[11]};
    const float* b0_all[2]  = {(const float*)d_in[7],  (const float*)d_in[12]};
    const float* w1_all[2]  = {(const float*)d_in[8],  (const float*)d_in[13]};
    const float* b1_all[2]  = {(const float*)d_in[9],  (const float*)d_in[14]};
    const float* ws_all[2]  = {(const float*)d_in[10], (const float*)d_in[15]};
    const float* fcw_all[2] = {(const float*)d_in[16], (const float*)d_in[18]};
    const float* fcb_all[2] = {(const float*)d_in[17], (const float*)d_in[19]};
    float* out = (float*)d_out;

    cudaFuncSetAttribute(k_hgemm, cudaFuncAttributeMaxDynamicSharedMemorySize,
                         SM_TOTAL);

    float *net0, *net1, *x2b, *hb, *cb, *bins, *cnt;
    cudaGetSymbolAddress((void**)&net0, g_net0);
    cudaGetSymbolAddress((void**)&net1, g_net1);
    cudaGetSymbolAddress((void**)&x2b,  g_x2);
    cudaGetSymbolAddress((void**)&hb,   g_h);
    cudaGetSymbolAddress((void**)&cb,   g_c);
    cudaGetSymbolAddress((void**)&bins, g_bins);
    cudaGetSymbolAddress((void**)&cnt,  g_cnt);

    const size_t binsBytes = (size_t)2 * 3 * BB * RRR * 128 * sizeof(float);
    const size_t cntBytes  = (size_t)3 * BB * RRR * sizeof(float);

    // weight prep: slot table
    WSrc ws;
    for (int z = 0; z < 2; z++) {
        for (int i = 0; i < NBLK; i++) {
            int sl = z * 26 + i * 5;
            ws.src[sl + 0] = w0_all[z] + (size_t)i * 256 * 128;
            ws.src[sl + 1] = w0_all[z] + (size_t)i * 256 * 128 + 128 * 128;
            ws.src[sl + 2] = w1_all[z] + (size_t)i * 128 * 128;
            ws.src[sl + 3] = ws_all[z] + (size_t)i * 256 * 128;
            ws.src[sl + 4] = ws_all[z] + (size_t)i * 256 * 128 + 128 * 128;
        }
        ws.src[z * 26 + 25] = fcw_all[z];
    }
    k_wprep<<<dim3(64, 52), 256>>>(ws);

    cudaMemsetAsync(cnt, 0, cntBytes);
    k_index<<<MM / 256, 256>>>(p);
    k_proj<<<(2 * MM * 256) / 256, 256>>>(p, p2, wp, bp, wp2, bp2);

    float* netCur = net0;
    float* netNext = net1;
    const dim3 gemmGrid(MM / 128, 1, 2);
    const dim3 rowBlk(128, 2);

    for (int i = 0; i < NBLK; i++) {
        if (i > 0) {
            cudaMemsetAsync(bins, 0xFF, binsBytes);
            k_scatter_max3<<<MM, rowBlk>>>(netCur);
            k_gather3<<<MM, rowBlk>>>(x2b);
        }
        {   // h = relu(net)@w0a + relu(pooled)@w0b + b0
            GArgs a{};
            a.A[0] = netCur; a.A[1] = x2b;
            for (int z = 0; z < 2; z++) {
                a.slot[0][z] = z * 26 + i * 5 + 0;
                a.slot[1][z] = z * 26 + i * 5 + 1;
                a.bias[z] = b0_all[z] + (size_t)i * 128;
            }
            a.out = hb; a.nseg = 2; a.reluMask = 0b11;
            k_hgemm<<<gemmGrid, 256, SM_TOTAL>>>(a);
        }
        {   // next = relu(h)@w1 + net@wsa + pooled@wsb + b1
            GArgs a{};
            a.A[0] = hb; a.A[1] = netCur; a.A[2] = x2b;
            for (int z = 0; z < 2; z++) {
                a.slot[0][z] = z * 26 + i * 5 + 2;
                a.slot[1][z] = z * 26 + i * 5 + 3;
                a.slot[2][z] = z * 26 + i * 5 + 4;
                a.bias[z] = b1_all[z] + (size_t)i * 128;
            }
            a.out = netNext; a.nseg = 3; a.reluMask = 0b001;
            k_hgemm<<<gemmGrid, 256, SM_TOTAL>>>(a);
        }
        { float* t = netCur; netCur = netNext; netNext = t; }
    }

    {   // c = net @ fc_w + fc_b
        GArgs a{};
        a.A[0] = netCur;
        for (int z = 0; z < 2; z++) {
            a.slot[0][z] = z * 26 + 25;
            a.bias[z] = fcb_all[z];
        }
        a.out = cb; a.nseg = 1; a.reluMask = 0;
        k_hgemm<<<gemmGrid, 256, SM_TOTAL>>>(a);
    }

    cudaMemsetAsync(bins, 0, binsBytes);
    k_scatter_mean3<<<MM, rowBlk>>>(cb);
    k_writeout<<<dim3(RRR / 32, 128 / 32, 6 * BB), dim3(32, 32)>>>(out);
}